// round 2
// baseline (speedup 1.0000x reference)
#include <cuda_runtime.h>
#include <cuda_bf16.h>

// PairwiseMLPLinkPredictor: out[i] = MLP( x[u_i] * x[v_i] )
// MLP: relu(f@W1+b1) -> relu(h@W2+b2) -> h2@W3+b3
// D=256, H=256, H/2=128, E=1e6 pairs.
//
// Fused single kernel, 64 pairs per block, 256 threads.
// fp32 register-tiled GEMMs; FFMA-pipe bound (~5.5-6.5ms predicted on sm_103a).
// R1 fix: edge_pairs is int32 (JAX demotes int64 without x64), was read as i64.

#define MT   64      // pairs per block
#define FS   260     // feats / h1 row stride in floats (256 + 4 pad, 16B-multiple)
#define H2S  132     // h2 row stride in floats (128 + 4 pad)

__global__ __launch_bounds__(256, 1)
void pairwise_mlp_kernel(const float* __restrict__ x,
                         const float* __restrict__ W1, const float* __restrict__ b1,
                         const float* __restrict__ W2, const float* __restrict__ b2,
                         const float* __restrict__ W3, const float* __restrict__ b3,
                         const int* __restrict__ pairs,
                         float* __restrict__ out, int E, int N)
{
    extern __shared__ float smem[];
    float* fe  = smem;                 // [64][260] pair features
    float* h1  = smem + MT * FS;       // [64][260] hidden layer 1 (256 used)
    float* h2  = fe;                   // [64][132] hidden layer 2, overlays fe
    float* w3s = smem + 2 * MT * FS;   // [128]

    const int tid = threadIdx.x;
    const long long base = (long long)blockIdx.x * MT;

    // stage W3 into smem
    if (tid < 128) w3s[tid] = W3[tid];

    // ---------------- gather: feats[m][k] = x[u][k] * x[v][k] ----------------
    {
        const int m = tid >> 2;        // 0..63
        const int q = tid & 3;         // k quarter
        long long gm = base + m;
        int u = 0, v = 0;
        if (gm < E) { u = pairs[2 * gm]; v = pairs[2 * gm + 1]; }
        // defensive clamp (cheap; protects against any index surprises)
        u = min(max(u, 0), N - 1);
        v = min(max(v, 0), N - 1);
        const float4* xu = (const float4*)(x + (size_t)u * 256);
        const float4* xv = (const float4*)(x + (size_t)v * 256);
        float4* frow = (float4*)(fe + m * FS);   // FS/4 = 65 float4 per row
        #pragma unroll
        for (int t = 0; t < 16; ++t) {
            int k4 = q * 16 + t;
            float4 a = __ldg(xu + k4);
            float4 c = __ldg(xv + k4);
            float4 f;
            f.x = a.x * c.x; f.y = a.y * c.y; f.z = a.z * c.z; f.w = a.w * c.w;
            frow[k4] = f;
        }
    }
    __syncthreads();

    const int wa = tid >> 5;   // warp id 0..7 -> row group (8 rows)
    const int lb = tid & 31;   // lane      -> col group

    // ---------------- GEMM1: h1 = relu(fe @ W1 + b1), [64][256] ----------------
    {
        float acc[8][8];
        #pragma unroll
        for (int i = 0; i < 8; i++)
            #pragma unroll
            for (int j = 0; j < 8; j++) acc[i][j] = 0.f;

        #pragma unroll 1
        for (int k0 = 0; k0 < 256; k0 += 4) {
            float f[8][4];
            #pragma unroll
            for (int i = 0; i < 8; i++) {
                float4 t = *(const float4*)&fe[(wa * 8 + i) * FS + k0];
                f[i][0] = t.x; f[i][1] = t.y; f[i][2] = t.z; f[i][3] = t.w;
            }
            #pragma unroll
            for (int kk = 0; kk < 4; kk++) {
                float4 w0 = __ldg((const float4*)(W1 + (k0 + kk) * 256 + lb * 8));
                float4 w1 = __ldg((const float4*)(W1 + (k0 + kk) * 256 + lb * 8 + 4));
                float w[8] = {w0.x, w0.y, w0.z, w0.w, w1.x, w1.y, w1.z, w1.w};
                #pragma unroll
                for (int i = 0; i < 8; i++)
                    #pragma unroll
                    for (int j = 0; j < 8; j++)
                        acc[i][j] = fmaf(f[i][kk], w[j], acc[i][j]);
            }
        }

        // epilogue: +b1, relu, store to h1
        float4 bv0 = __ldg((const float4*)(b1 + lb * 8));
        float4 bv1 = __ldg((const float4*)(b1 + lb * 8 + 4));
        float bb[8] = {bv0.x, bv0.y, bv0.z, bv0.w, bv1.x, bv1.y, bv1.z, bv1.w};
        #pragma unroll
        for (int i = 0; i < 8; i++) {
            float4 o0, o1;
            o0.x = fmaxf(acc[i][0] + bb[0], 0.f);
            o0.y = fmaxf(acc[i][1] + bb[1], 0.f);
            o0.z = fmaxf(acc[i][2] + bb[2], 0.f);
            o0.w = fmaxf(acc[i][3] + bb[3], 0.f);
            o1.x = fmaxf(acc[i][4] + bb[4], 0.f);
            o1.y = fmaxf(acc[i][5] + bb[5], 0.f);
            o1.z = fmaxf(acc[i][6] + bb[6], 0.f);
            o1.w = fmaxf(acc[i][7] + bb[7], 0.f);
            *(float4*)&h1[(wa * 8 + i) * FS + lb * 8]     = o0;
            *(float4*)&h1[(wa * 8 + i) * FS + lb * 8 + 4] = o1;
        }
    }
    __syncthreads();

    // ---------------- GEMM2: h2 = relu(h1 @ W2 + b2), [64][128] ----------------
    {
        float acc[8][4];
        #pragma unroll
        for (int i = 0; i < 8; i++)
            #pragma unroll
            for (int j = 0; j < 4; j++) acc[i][j] = 0.f;

        #pragma unroll 1
        for (int k0 = 0; k0 < 256; k0 += 4) {
            float f[8][4];
            #pragma unroll
            for (int i = 0; i < 8; i++) {
                float4 t = *(const float4*)&h1[(wa * 8 + i) * FS + k0];
                f[i][0] = t.x; f[i][1] = t.y; f[i][2] = t.z; f[i][3] = t.w;
            }
            #pragma unroll
            for (int kk = 0; kk < 4; kk++) {
                float4 w = __ldg((const float4*)(W2 + (k0 + kk) * 128 + lb * 4));
                #pragma unroll
                for (int i = 0; i < 8; i++) {
                    acc[i][0] = fmaf(f[i][kk], w.x, acc[i][0]);
                    acc[i][1] = fmaf(f[i][kk], w.y, acc[i][1]);
                    acc[i][2] = fmaf(f[i][kk], w.z, acc[i][2]);
                    acc[i][3] = fmaf(f[i][kk], w.w, acc[i][3]);
                }
            }
        }

        float4 bv = __ldg((const float4*)(b2 + lb * 4));
        #pragma unroll
        for (int i = 0; i < 8; i++) {
            float4 o;
            o.x = fmaxf(acc[i][0] + bv.x, 0.f);
            o.y = fmaxf(acc[i][1] + bv.y, 0.f);
            o.z = fmaxf(acc[i][2] + bv.z, 0.f);
            o.w = fmaxf(acc[i][3] + bv.w, 0.f);
            *(float4*)&h2[(wa * 8 + i) * H2S + lb * 4] = o;
        }
    }
    __syncthreads();

    // ---------------- GEMM3: scores = h2 @ W3 + b3 ----------------
    {
        const int m = tid >> 2;     // pair within block
        const int q = tid & 3;      // k quarter (32 each)
        float s = 0.f;
        #pragma unroll
        for (int t = 0; t < 8; t++) {
            float4 hv = *(const float4*)&h2[m * H2S + q * 32 + t * 4];
            float4 wv = *(const float4*)&w3s[q * 32 + t * 4];
            s = fmaf(hv.x, wv.x, s);
            s = fmaf(hv.y, wv.y, s);
            s = fmaf(hv.z, wv.z, s);
            s = fmaf(hv.w, wv.w, s);
        }
        // reduce across the 4 lanes holding the same m (lanes are consecutive)
        s += __shfl_xor_sync(0xffffffffu, s, 1);
        s += __shfl_xor_sync(0xffffffffu, s, 2);
        long long gm = base + m;
        if (q == 0 && gm < E) out[gm] = s + __ldg(b3);
    }
}

extern "C" void kernel_launch(void* const* d_in, const int* in_sizes, int n_in,
                              void* d_out, int out_size)
{
    const float* x     = (const float*)d_in[0];
    const float* W1    = (const float*)d_in[1];
    const float* b1    = (const float*)d_in[2];
    const float* W2    = (const float*)d_in[3];
    const float* b2    = (const float*)d_in[4];
    const float* W3    = (const float*)d_in[5];
    const float* b3    = (const float*)d_in[6];
    // d_in[7] = edge_index (unused by reference math)
    const int*   pairs = (const int*)d_in[8];   // int32 (JAX demotes int64)
    float* out = (float*)d_out;

    int E = in_sizes[8] / 2;
    int N = in_sizes[0] / 256;
    int grid = (E + MT - 1) / MT;
    size_t smem_bytes = (size_t)(2 * MT * FS + 128) * sizeof(float);  // 133,632 B

    cudaFuncSetAttribute(pairwise_mlp_kernel,
                         cudaFuncAttributeMaxDynamicSharedMemorySize,
                         (int)smem_bytes);

    pairwise_mlp_kernel<<<grid, 256, smem_bytes>>>(
        x, W1, b1, W2, b2, W3, b3, pairs, out, E, N);
}

// round 6
// speedup vs baseline: 1.0290x; 1.0290x over previous
#include <cuda_runtime.h>
#include <cuda_bf16.h>

// PairwiseMLPLinkPredictor: out[i] = MLP( x[u_i] * x[v_i] )
// D=256, H=256, H/2=128, E=1e6.
//
// R3 (3rd resubmit after infra timeouts): 512 threads/block (16 warps, occ 25%),
// coalesced weight LDG.128 (lane-contiguous float4), packed fma.rn.f32x2
// (2 M-rows per 64-bit acc).

#define MT   64      // pairs per block
#define FS   260     // feats/h1 row stride (floats)
#define H2S  132     // h2 row stride (floats)

__device__ __forceinline__ unsigned long long pack2(float lo, float hi) {
    unsigned long long r;
    asm("mov.b64 %0, {%1, %2};" : "=l"(r) : "f"(lo), "f"(hi));
    return r;
}
__device__ __forceinline__ void unpack2(unsigned long long v, float& lo, float& hi) {
    asm("mov.b64 {%0, %1}, %2;" : "=f"(lo), "=f"(hi) : "l"(v));
}
__device__ __forceinline__ unsigned long long ffma2(unsigned long long a,
                                                    unsigned long long b,
                                                    unsigned long long c) {
    unsigned long long d;
    asm("fma.rn.f32x2 %0, %1, %2, %3;" : "=l"(d) : "l"(a), "l"(b), "l"(c));
    return d;
}

__global__ __launch_bounds__(512, 1)
void pairwise_mlp_kernel(const float* __restrict__ x,
                         const float* __restrict__ W1, const float* __restrict__ b1,
                         const float* __restrict__ W2, const float* __restrict__ b2,
                         const float* __restrict__ W3, const float* __restrict__ b3,
                         const int* __restrict__ pairs,
                         float* __restrict__ out, int E, int N)
{
    extern __shared__ float smem[];
    float* fe  = smem;                 // [64][260]
    float* h1  = smem + MT * FS;       // [64][260]
    float* h2  = fe;                   // [64][132] overlays fe
    float* w3s = smem + 2 * MT * FS;   // [128]

    const int tid = threadIdx.x;
    const long long base = (long long)blockIdx.x * MT;

    if (tid < 128) w3s[tid] = W3[tid];

    // ---------------- gather: feats[m][k] = x[u][k] * x[v][k] ----------------
    {
        const int m = tid >> 3;        // 0..63
        const int q = tid & 7;         // eighth of the row
        long long gm = base + m;
        int u = 0, v = 0;
        if (gm < E) { u = pairs[2 * gm]; v = pairs[2 * gm + 1]; }
        u = min(max(u, 0), N - 1);
        v = min(max(v, 0), N - 1);
        const float4* xu = (const float4*)(x + (size_t)u * 256);
        const float4* xv = (const float4*)(x + (size_t)v * 256);
        float4* frow = (float4*)(fe + m * FS);
        #pragma unroll
        for (int t = 0; t < 8; ++t) {
            int k4 = q * 8 + t;
            float4 a = __ldg(xu + k4);
            float4 c = __ldg(xv + k4);
            float4 f;
            f.x = a.x * c.x; f.y = a.y * c.y; f.z = a.z * c.z; f.w = a.w * c.w;
            frow[k4] = f;
        }
    }
    __syncthreads();

    // ---------------- GEMM1: h1 = relu(fe @ W1 + b1), [64][256] ----------------
    // thread (r, c): r = tid>>6 (8 rows r*8..r*8+7, as 4 row-pairs), c = tid&63 (4 cols)
    {
        const int r = tid >> 6;
        const int c = tid & 63;
        unsigned long long acc[4][4];
        #pragma unroll
        for (int p = 0; p < 4; p++)
            #pragma unroll
            for (int j = 0; j < 4; j++) acc[p][j] = 0ull;

        #pragma unroll 1
        for (int k0 = 0; k0 < 256; k0 += 4) {
            float4 f4[8];
            #pragma unroll
            for (int i = 0; i < 8; i++)
                f4[i] = *(const float4*)&fe[(r * 8 + i) * FS + k0];   // LDS.128 broadcast

            #pragma unroll
            for (int kk = 0; kk < 4; kk++) {
                float4 w4 = __ldg((const float4*)(W1 + (k0 + kk) * 256 + c * 4)); // coalesced
                unsigned long long w2[4];
                w2[0] = pack2(w4.x, w4.x); w2[1] = pack2(w4.y, w4.y);
                w2[2] = pack2(w4.z, w4.z); w2[3] = pack2(w4.w, w4.w);
                #pragma unroll
                for (int p = 0; p < 4; p++) {
                    float flo = (kk == 0 ? f4[2*p].x : kk == 1 ? f4[2*p].y : kk == 2 ? f4[2*p].z : f4[2*p].w);
                    float fhi = (kk == 0 ? f4[2*p+1].x : kk == 1 ? f4[2*p+1].y : kk == 2 ? f4[2*p+1].z : f4[2*p+1].w);
                    unsigned long long fp = pack2(flo, fhi);
                    #pragma unroll
                    for (int j = 0; j < 4; j++)
                        acc[p][j] = ffma2(fp, w2[j], acc[p][j]);
                }
            }
        }

        float4 bv = __ldg((const float4*)(b1 + c * 4));
        float bb[4] = {bv.x, bv.y, bv.z, bv.w};
        #pragma unroll
        for (int p = 0; p < 4; p++) {
            float4 olo, ohi;
            float lo, hi;
            unpack2(acc[p][0], lo, hi); olo.x = fmaxf(lo + bb[0], 0.f); ohi.x = fmaxf(hi + bb[0], 0.f);
            unpack2(acc[p][1], lo, hi); olo.y = fmaxf(lo + bb[1], 0.f); ohi.y = fmaxf(hi + bb[1], 0.f);
            unpack2(acc[p][2], lo, hi); olo.z = fmaxf(lo + bb[2], 0.f); ohi.z = fmaxf(hi + bb[2], 0.f);
            unpack2(acc[p][3], lo, hi); olo.w = fmaxf(lo + bb[3], 0.f); ohi.w = fmaxf(hi + bb[3], 0.f);
            *(float4*)&h1[(r * 8 + 2*p    ) * FS + c * 4] = olo;
            *(float4*)&h1[(r * 8 + 2*p + 1) * FS + c * 4] = ohi;
        }
    }
    __syncthreads();

    // ---------------- GEMM2: h2 = relu(h1 @ W2 + b2), [64][128] ----------------
    // thread (rr, c): rr = tid>>5 (4 rows rr*4.., as 2 pairs), c = tid&31 (4 cols)
    {
        const int rr = tid >> 5;
        const int c  = tid & 31;
        unsigned long long acc[2][4];
        #pragma unroll
        for (int p = 0; p < 2; p++)
            #pragma unroll
            for (int j = 0; j < 4; j++) acc[p][j] = 0ull;

        #pragma unroll 1
        for (int k0 = 0; k0 < 256; k0 += 4) {
            float4 f4[4];
            #pragma unroll
            for (int i = 0; i < 4; i++)
                f4[i] = *(const float4*)&h1[(rr * 4 + i) * FS + k0];  // broadcast

            #pragma unroll
            for (int kk = 0; kk < 4; kk++) {
                float4 w4 = __ldg((const float4*)(W2 + (k0 + kk) * 128 + c * 4)); // coalesced
                unsigned long long w2[4];
                w2[0] = pack2(w4.x, w4.x); w2[1] = pack2(w4.y, w4.y);
                w2[2] = pack2(w4.z, w4.z); w2[3] = pack2(w4.w, w4.w);
                #pragma unroll
                for (int p = 0; p < 2; p++) {
                    float flo = (kk == 0 ? f4[2*p].x : kk == 1 ? f4[2*p].y : kk == 2 ? f4[2*p].z : f4[2*p].w);
                    float fhi = (kk == 0 ? f4[2*p+1].x : kk == 1 ? f4[2*p+1].y : kk == 2 ? f4[2*p+1].z : f4[2*p+1].w);
                    unsigned long long fp = pack2(flo, fhi);
                    #pragma unroll
                    for (int j = 0; j < 4; j++)
                        acc[p][j] = ffma2(fp, w2[j], acc[p][j]);
                }
            }
        }

        float4 bv = __ldg((const float4*)(b2 + c * 4));
        float bb[4] = {bv.x, bv.y, bv.z, bv.w};
        #pragma unroll
        for (int p = 0; p < 2; p++) {
            float4 olo, ohi;
            float lo, hi;
            unpack2(acc[p][0], lo, hi); olo.x = fmaxf(lo + bb[0], 0.f); ohi.x = fmaxf(hi + bb[0], 0.f);
            unpack2(acc[p][1], lo, hi); olo.y = fmaxf(lo + bb[1], 0.f); ohi.y = fmaxf(hi + bb[1], 0.f);
            unpack2(acc[p][2], lo, hi); olo.z = fmaxf(lo + bb[2], 0.f); ohi.z = fmaxf(hi + bb[2], 0.f);
            unpack2(acc[p][3], lo, hi); olo.w = fmaxf(lo + bb[3], 0.f); ohi.w = fmaxf(hi + bb[3], 0.f);
            *(float4*)&h2[(rr * 4 + 2*p    ) * H2S + c * 4] = olo;
            *(float4*)&h2[(rr * 4 + 2*p + 1) * H2S + c * 4] = ohi;
        }
    }
    __syncthreads();

    // ---------------- GEMM3: scores = h2 @ W3 + b3 ----------------
    {
        const int m = tid >> 3;     // pair within block
        const int q = tid & 7;      // 16 k-values each
        float s = 0.f;
        #pragma unroll
        for (int t = 0; t < 4; t++) {
            float4 hv = *(const float4*)&h2[m * H2S + q * 16 + t * 4];
            float4 wv = *(const float4*)&w3s[q * 16 + t * 4];
            s = fmaf(hv.x, wv.x, s);
            s = fmaf(hv.y, wv.y, s);
            s = fmaf(hv.z, wv.z, s);
            s = fmaf(hv.w, wv.w, s);
        }
        s += __shfl_xor_sync(0xffffffffu, s, 1);
        s += __shfl_xor_sync(0xffffffffu, s, 2);
        s += __shfl_xor_sync(0xffffffffu, s, 4);
        long long gm = base + m;
        if (q == 0 && gm < E) out[gm] = s + __ldg(b3);
    }
}

extern "C" void kernel_launch(void* const* d_in, const int* in_sizes, int n_in,
                              void* d_out, int out_size)
{
    const float* x     = (const float*)d_in[0];
    const float* W1    = (const float*)d_in[1];
    const float* b1    = (const float*)d_in[2];
    const float* W2    = (const float*)d_in[3];
    const float* b2    = (const float*)d_in[4];
    const float* W3    = (const float*)d_in[5];
    const float* b3    = (const float*)d_in[6];
    // d_in[7] = edge_index (unused)
    const int*   pairs = (const int*)d_in[8];   // int32
    float* out = (float*)d_out;

    int E = in_sizes[8] / 2;
    int N = in_sizes[0] / 256;
    int grid = (E + MT - 1) / MT;
    size_t smem_bytes = (size_t)(2 * MT * FS + 128) * sizeof(float);  // 133,632 B

    cudaFuncSetAttribute(pairwise_mlp_kernel,
                         cudaFuncAttributeMaxDynamicSharedMemorySize,
                         (int)smem_bytes);

    pairwise_mlp_kernel<<<grid, 512, smem_bytes>>>(
        x, W1, b1, W2, b2, W3, b3, pairs, out, E, N);
}

// round 16
// speedup vs baseline: 2.2623x; 2.1986x over previous
#include <cuda_runtime.h>
#include <cuda_bf16.h>
#include <cstdint>

// PairwiseMLPLinkPredictor via warp-level mma.sync (HMMA) bf16 hi/lo split.
// tcgen05 is unavailable: harness PTX target is compute_103 (non-'a').
// Block = 128 pairs, 512 threads, 16 warps.
// GEMM1: [128x256]x[256x256], GEMM2: [128x256]x[256x128], dot-128 epilogue.

#define THREADS 512
#define MT      128

// smem byte offsets
#define FH   0           // feats/h hi  [128][264] bf16 = 67,584
#define FL   67584       // feats/h lo  [128][264] bf16
#define WB   135168      // weight chunk buffer (max 73,728) / later h2 f32 [128][132]
#define B1S  208896      // b1[256] f32
#define B2S  209920      // b2[128] f32
#define W3S  210432      // w3[128] f32
#define SM_TOTAL 210944

#define FSTR 528         // feats row stride bytes (264 bf16)
#define WSTR 144         // weight row stride bytes (72 bf16)

// Prepared weights: W^T, [chunk 0..3][split hi/lo][n][72 k bf16]
// W1: 4 chunks * 2 * 256 * 72 bf16 = 294,912 B = 18,432 uint4
// W2: 4 chunks * 2 * 128 * 72 bf16 = 147,456 B =  9,216 uint4
__device__ uint4 g_w1[18432];
__device__ uint4 g_w2[9216];

__device__ __forceinline__ uint32_t smem_u32(const void* p) {
    uint32_t a;
    asm("{ .reg .u64 t; cvta.to.shared.u64 t, %1; cvt.u32.u64 %0, t; }" : "=r"(a) : "l"(p));
    return a;
}
__device__ __forceinline__ uint32_t packbf(float f0, float f1) {   // lo half=f0, hi half=f1
    uint32_t r;
    asm("cvt.rn.bf16x2.f32 %0, %1, %2;" : "=r"(r) : "f"(f1), "f"(f0));
    return r;
}
__device__ __forceinline__ void ldsm4(uint32_t* r, uint32_t addr) {
    asm volatile("ldmatrix.sync.aligned.m8n8.x4.shared.b16 {%0,%1,%2,%3}, [%4];"
        : "=r"(r[0]), "=r"(r[1]), "=r"(r[2]), "=r"(r[3]) : "r"(addr));
}
__device__ __forceinline__ void ldsm2(uint32_t* r, uint32_t addr) {
    asm volatile("ldmatrix.sync.aligned.m8n8.x2.shared.b16 {%0,%1}, [%2];"
        : "=r"(r[0]), "=r"(r[1]) : "r"(addr));
}
__device__ __forceinline__ void mma16816(float* c, const uint32_t* a, const uint32_t* b) {
    asm volatile("mma.sync.aligned.m16n8k16.row.col.f32.bf16.bf16.f32 "
        "{%0,%1,%2,%3}, {%4,%5,%6,%7}, {%8,%9}, {%0,%1,%2,%3};"
        : "+f"(c[0]), "+f"(c[1]), "+f"(c[2]), "+f"(c[3])
        : "r"(a[0]), "r"(a[1]), "r"(a[2]), "r"(a[3]), "r"(b[0]), "r"(b[1]));
}

// --------------------------------------------------------------- prep kernel
__global__ void prep_weights(const float* __restrict__ W1, const float* __restrict__ W2) {
    int i = blockIdx.x * blockDim.x + threadIdx.x;
    if (i < 65536) {                       // W1: k 0..255, n 0..255
        int k = i >> 8, n = i & 255;
        float w = W1[k * 256 + n];
        __nv_bfloat16 h = __float2bfloat16(w);
        float lo = w - __bfloat162float(h);
        int c = k >> 6, kk = k & 63;
        __nv_bfloat16* base = (__nv_bfloat16*)g_w1;
        base[((size_t)(c * 2 + 0) * 256 + n) * 72 + kk] = h;
        base[((size_t)(c * 2 + 1) * 256 + n) * 72 + kk] = __float2bfloat16(lo);
    } else if (i < 65536 + 32768) {        // W2: k 0..255, n 0..127
        int j = i - 65536;
        int k = j >> 7, n = j & 127;
        float w = W2[k * 128 + n];
        __nv_bfloat16 h = __float2bfloat16(w);
        float lo = w - __bfloat162float(h);
        int c = k >> 6, kk = k & 63;
        __nv_bfloat16* base = (__nv_bfloat16*)g_w2;
        base[((size_t)(c * 2 + 0) * 128 + n) * 72 + kk] = h;
        base[((size_t)(c * 2 + 1) * 128 + n) * 72 + kk] = __float2bfloat16(lo);
    }
}

// ---------------------------------------------------------------- main kernel
__global__ __launch_bounds__(THREADS, 1)
void pairwise_mlp_hmma(const float* __restrict__ x,
                       const float* __restrict__ b1g, const float* __restrict__ b2g,
                       const float* __restrict__ W3g, const float* __restrict__ b3g,
                       const int* __restrict__ pairs,
                       float* __restrict__ out, int E, int N)
{
    extern __shared__ unsigned char smem[];
    const uint32_t sb = smem_u32(smem);
    const int tid  = threadIdx.x;
    const int wz   = tid >> 5;
    const int lane = tid & 31;
    const long long base = (long long)blockIdx.x * MT;

    float* b1s = (float*)(smem + B1S);
    float* b2s = (float*)(smem + B2S);
    float* w3s = (float*)(smem + W3S);
    if (tid < 256)       b1s[tid] = b1g[tid];
    else if (tid < 384)  b2s[tid - 256] = b2g[tid - 256];
    else                 w3s[tid - 384] = W3g[tid - 384];

    // lane-derived ldmatrix offsets
    const uint32_t a_row = (lane & 7) + ((lane >> 3) & 1) * 8;
    const uint32_t a_kof = (uint32_t)(lane >> 4) * 8;
    const int lb = lane & 15;
    const uint32_t b_row = lb & 7;
    const uint32_t b_kof = (uint32_t)(lb >> 3) * 8;
    const int cr = lane >> 2;          // acc row within 16
    const int cc = (lane & 3) * 2;     // acc col within 8

    // ---------------- gather: feats hi/lo into smem ----------------
    {
        const int m = tid >> 2, q = tid & 3;
        long long gm = base + m;
        int u = 0, v = 0;
        if (gm < E) { u = pairs[2 * gm]; v = pairs[2 * gm + 1]; }
        u = min(max(u, 0), N - 1);
        v = min(max(v, 0), N - 1);
        const float4* xu = (const float4*)(x + (size_t)u * 256);
        const float4* xv = (const float4*)(x + (size_t)v * 256);
        unsigned char* fh = smem + FH + m * FSTR + q * 128;
        unsigned char* fl = smem + FL + m * FSTR + q * 128;
        #pragma unroll
        for (int i = 0; i < 16; i++) {
            float4 a = __ldg(xu + q * 16 + i);
            float4 b = __ldg(xv + q * 16 + i);
            float f0 = a.x * b.x, f1 = a.y * b.y, f2 = a.z * b.z, f3 = a.w * b.w;
            uint32_t h01 = packbf(f0, f1), h23 = packbf(f2, f3);
            __nv_bfloat162 p01 = *(__nv_bfloat162*)&h01;
            __nv_bfloat162 p23 = *(__nv_bfloat162*)&h23;
            uint32_t l01 = packbf(f0 - __bfloat162float(p01.x), f1 - __bfloat162float(p01.y));
            uint32_t l23 = packbf(f2 - __bfloat162float(p23.x), f3 - __bfloat162float(p23.y));
            *(uint32_t*)(fh + i * 8)     = h01;
            *(uint32_t*)(fh + i * 8 + 4) = h23;
            *(uint32_t*)(fl + i * 8)     = l01;
            *(uint32_t*)(fl + i * 8 + 4) = l23;
        }
    }
    __syncthreads();

    // ---------------- GEMM1: h = relu(feats @ W1 + b1), N=256 ----------------
    {
        const int mw = (wz & 3) * 32;
        const int nw = (wz >> 2) * 64;
        float acc[2][8][4];
        #pragma unroll
        for (int mt = 0; mt < 2; mt++)
            #pragma unroll
            for (int nt = 0; nt < 8; nt++)
                #pragma unroll
                for (int j = 0; j < 4; j++) acc[mt][nt][j] = 0.f;

        #pragma unroll 1
        for (int c = 0; c < 4; c++) {
            const uint4* src = g_w1 + c * 4608;
            uint4* dst = (uint4*)(smem + WB);
            for (int i = tid; i < 4608; i += THREADS) dst[i] = __ldg(src + i);
            __syncthreads();
            #pragma unroll
            for (int ks = 0; ks < 4; ks++) {
                uint32_t ah[2][4], al[2][4];
                #pragma unroll
                for (int mt = 0; mt < 2; mt++) {
                    uint32_t ra = (mw + mt * 16 + a_row) * FSTR + (c * 64 + ks * 16 + a_kof) * 2;
                    ldsm4(ah[mt], sb + FH + ra);
                    ldsm4(al[mt], sb + FL + ra);
                }
                #pragma unroll
                for (int nt = 0; nt < 8; nt++) {
                    uint32_t rb = (nw + nt * 8 + b_row) * WSTR + (ks * 16 + b_kof) * 2;
                    uint32_t bh[2], bl[2];
                    ldsm2(bh, sb + WB + rb);
                    ldsm2(bl, sb + WB + 36864 + rb);
                    #pragma unroll
                    for (int mt = 0; mt < 2; mt++) {
                        mma16816(acc[mt][nt], ah[mt], bh);
                        mma16816(acc[mt][nt], ah[mt], bl);
                        mma16816(acc[mt][nt], al[mt], bh);
                    }
                }
            }
            __syncthreads();
        }

        // epilogue 1: bias+relu, re-split into feats arrays
        #pragma unroll
        for (int mt = 0; mt < 2; mt++)
            #pragma unroll
            for (int nt = 0; nt < 8; nt++) {
                int m0 = mw + mt * 16 + cr;
                int n0 = nw + nt * 8 + cc;
                float bb0 = b1s[n0], bb1 = b1s[n0 + 1];
                float v0 = fmaxf(acc[mt][nt][0] + bb0, 0.f);
                float v1 = fmaxf(acc[mt][nt][1] + bb1, 0.f);
                float v2 = fmaxf(acc[mt][nt][2] + bb0, 0.f);
                float v3 = fmaxf(acc[mt][nt][3] + bb1, 0.f);
                uint32_t h01 = packbf(v0, v1);
                __nv_bfloat162 p01 = *(__nv_bfloat162*)&h01;
                uint32_t l01 = packbf(v0 - __bfloat162float(p01.x), v1 - __bfloat162float(p01.y));
                uint32_t h23 = packbf(v2, v3);
                __nv_bfloat162 p23 = *(__nv_bfloat162*)&h23;
                uint32_t l23 = packbf(v2 - __bfloat162float(p23.x), v3 - __bfloat162float(p23.y));
                *(uint32_t*)(smem + FH + m0 * FSTR + n0 * 2)       = h01;
                *(uint32_t*)(smem + FL + m0 * FSTR + n0 * 2)       = l01;
                *(uint32_t*)(smem + FH + (m0 + 8) * FSTR + n0 * 2) = h23;
                *(uint32_t*)(smem + FL + (m0 + 8) * FSTR + n0 * 2) = l23;
            }
    }
    __syncthreads();

    // ---------------- GEMM2: h2 = relu(h @ W2 + b2), N=128 ----------------
    {
        const int mw = (wz & 3) * 32;
        const int nw = (wz >> 2) * 32;
        float acc[2][4][4];
        #pragma unroll
        for (int mt = 0; mt < 2; mt++)
            #pragma unroll
            for (int nt = 0; nt < 4; nt++)
                #pragma unroll
                for (int j = 0; j < 4; j++) acc[mt][nt][j] = 0.f;

        #pragma unroll 1
        for (int c = 0; c < 4; c++) {
            const uint4* src = g_w2 + c * 2304;
            uint4* dst = (uint4*)(smem + WB);
            for (int i = tid; i < 2304; i += THREADS) dst[i] = __ldg(src + i);
            __syncthreads();
            #pragma unroll
            for (int ks = 0; ks < 4; ks++) {
                uint32_t ah[2][4], al[2][4];
                #pragma unroll
                for (int mt = 0; mt < 2; mt++) {
                    uint32_t ra = (mw + mt * 16 + a_row) * FSTR + (c * 64 + ks * 16 + a_kof) * 2;
                    ldsm4(ah[mt], sb + FH + ra);
                    ldsm4(al[mt], sb + FL + ra);
                }
                #pragma unroll
                for (int nt = 0; nt < 4; nt++) {
                    uint32_t rb = (nw + nt * 8 + b_row) * WSTR + (ks * 16 + b_kof) * 2;
                    uint32_t bh[2], bl[2];
                    ldsm2(bh, sb + WB + rb);
                    ldsm2(bl, sb + WB + 18432 + rb);
                    #pragma unroll
                    for (int mt = 0; mt < 2; mt++) {
                        mma16816(acc[mt][nt], ah[mt], bh);
                        mma16816(acc[mt][nt], ah[mt], bl);
                        mma16816(acc[mt][nt], al[mt], bh);
                    }
                }
            }
            __syncthreads();
        }

        // epilogue 2: bias+relu to f32 h2 (overlays weight buffer)
        #pragma unroll
        for (int mt = 0; mt < 2; mt++)
            #pragma unroll
            for (int nt = 0; nt < 4; nt++) {
                int m0 = mw + mt * 16 + cr;
                int n0 = nw + nt * 8 + cc;
                float bb0 = b2s[n0], bb1 = b2s[n0 + 1];
                *(float*)(smem + WB + m0 * FSTR + n0 * 4)           = fmaxf(acc[mt][nt][0] + bb0, 0.f);
                *(float*)(smem + WB + m0 * FSTR + (n0 + 1) * 4)     = fmaxf(acc[mt][nt][1] + bb1, 0.f);
                *(float*)(smem + WB + (m0 + 8) * FSTR + n0 * 4)     = fmaxf(acc[mt][nt][2] + bb0, 0.f);
                *(float*)(smem + WB + (m0 + 8) * FSTR + (n0 + 1) * 4) = fmaxf(acc[mt][nt][3] + bb1, 0.f);
            }
    }
    __syncthreads();

    // ---------------- GEMM3: out = h2 . w3 + b3 ----------------
    if (tid < MT) {
        const float4* row = (const float4*)(smem + WB + tid * FSTR);
        const float4* wv  = (const float4*)w3s;
        float s = 0.f;
        #pragma unroll
        for (int i = 0; i < 32; i++) {
            float4 h = row[i], w = wv[i];
            s = fmaf(h.x, w.x, s);
            s = fmaf(h.y, w.y, s);
            s = fmaf(h.z, w.z, s);
            s = fmaf(h.w, w.w, s);
        }
        long long gm = base + tid;
        if (gm < E) out[gm] = s + __ldg(b3g);
    }
}

extern "C" void kernel_launch(void* const* d_in, const int* in_sizes, int n_in,
                              void* d_out, int out_size)
{
    const float* x     = (const float*)d_in[0];
    const float* W1    = (const float*)d_in[1];
    const float* b1    = (const float*)d_in[2];
    const float* W2    = (const float*)d_in[3];
    const float* b2    = (const float*)d_in[4];
    const float* W3    = (const float*)d_in[5];
    const float* b3    = (const float*)d_in[6];
    // d_in[7] = edge_index (unused)
    const int*   pairs = (const int*)d_in[8];   // int32
    float* out = (float*)d_out;

    int E = in_sizes[8] / 2;
    int N = in_sizes[0] / 256;

    prep_weights<<<(65536 + 32768 + 255) / 256, 256>>>(W1, W2);

    cudaFuncSetAttribute(pairwise_mlp_hmma,
                         cudaFuncAttributeMaxDynamicSharedMemorySize, SM_TOTAL);
    int grid = (E + MT - 1) / MT;
    pairwise_mlp_hmma<<<grid, THREADS, SM_TOTAL>>>(x, b1, b2, W3, b3, pairs, out, E, N);
}